// round 4
// baseline (speedup 1.0000x reference)
#include <cuda_runtime.h>
#include <cstdint>
#include <cstddef>

// ---------------------------------------------------------------------------
// Problem constants
// ---------------------------------------------------------------------------
#define NB   8
#define NH   4
#define SEQ  2048
#define DM   64
#define SSTR 2052   // score row stride (floats)

// ---------------------------------------------------------------------------
// Static device scratch (no cudaMalloc allowed)
// ---------------------------------------------------------------------------
__device__ float g_gates[3 * NB];
__device__ int   g_mask_mode;                         // 1 = int32 mask, 0 = byte mask
__device__ float g_Qe[(size_t)NB * NH * SEQ * 128];   // 33.5 MB
__device__ float g_Ke[(size_t)NB * NH * SEQ * 128];   // 33.5 MB
__device__ float g_Ve[(size_t)NB * NH * SEQ * 64];    // 16.8 MB
__device__ float g_ctx[(size_t)NB * SEQ * 256];       // 16.8 MB

// ---------------------------------------------------------------------------
// Helpers
// ---------------------------------------------------------------------------
__device__ __forceinline__ float tf32r(float x) {
    float y;
    asm("cvt.rna.tf32.f32 %0, %1;" : "=f"(y) : "f"(x));
    return y;
}

__device__ __forceinline__ void mma_tf32(float& c0, float& c1, float& c2, float& c3,
                                         unsigned a0, unsigned a1, unsigned a2, unsigned a3,
                                         unsigned b0, unsigned b1) {
    asm volatile(
        "mma.sync.aligned.m16n8k8.row.col.f32.tf32.tf32.f32 "
        "{%0,%1,%2,%3},{%4,%5,%6,%7},{%8,%9},{%0,%1,%2,%3};"
        : "+f"(c0), "+f"(c1), "+f"(c2), "+f"(c3)
        : "r"(a0), "r"(a1), "r"(a2), "r"(a3), "r"(b0), "r"(b1));
}

// ---------------------------------------------------------------------------
// Kernel D: detect mask encoding. In int32 encoding (values 0/1 LE) the bytes
// at offsets 4i+1..4i+3 are all zero; in byte encoding ~50% are nonzero.
// ---------------------------------------------------------------------------
__global__ void detect_mask_kernel(const unsigned char* __restrict__ m) {
    int found = 0;
    for (int i = threadIdx.x; i < 1024; i += 32)
        if (m[i * 4 + 1] | m[i * 4 + 2] | m[i * 4 + 3]) found = 1;
    for (int o = 16; o; o >>= 1)
        found |= __shfl_xor_sync(0xffffffffu, found, o);
    if (threadIdx.x == 0) g_mask_mode = found ? 0 : 1;
}

// ---------------------------------------------------------------------------
// Kernel 0: scalar gates  S = relu(u @ s1) @ s2  per batch
// ---------------------------------------------------------------------------
__global__ void gates_kernel(const float* __restrict__ u,
                             const float* __restrict__ sq1, const float* __restrict__ sq2,
                             const float* __restrict__ sk1, const float* __restrict__ sk2,
                             const float* __restrict__ sv1, const float* __restrict__ sv2) {
    const int b = blockIdx.x;
    const int lane = threadIdx.x;
    float hq = 0.f, hk = 0.f, hv = 0.f;
    for (int d = 0; d < DM; ++d) {
        float uv = u[b * DM + d];
        hq += uv * sq1[d * 32 + lane];
        hk += uv * sk1[d * 32 + lane];
        hv += uv * sv1[d * 32 + lane];
    }
    hq = fmaxf(hq, 0.f) * sq2[lane];
    hk = fmaxf(hk, 0.f) * sk2[lane];
    hv = fmaxf(hv, 0.f) * sv2[lane];
    for (int off = 16; off; off >>= 1) {
        hq += __shfl_xor_sync(0xffffffffu, hq, off);
        hk += __shfl_xor_sync(0xffffffffu, hk, off);
        hv += __shfl_xor_sync(0xffffffffu, hv, off);
    }
    if (lane == 0) {
        g_gates[b]      = hq;
        g_gates[8 + b]  = hk;
        g_gates[16 + b] = hv;
    }
}

// ---------------------------------------------------------------------------
// Kernel 1: projections. Qe=[Q|uQ*Sq]*0.125 (tf32), Ke=[K|uK*Sk] (tf32),
// Ve=V+uV*Sv.  64 rows per CTA, 256 threads.
// ---------------------------------------------------------------------------
#define PROJ_SMEM_BYTES ((64*68 + 3*64*68 + 64*260) * 4)

__global__ void __launch_bounds__(256) proj_kernel(
    const float* __restrict__ x,
    const float* __restrict__ wq, const float* __restrict__ wk, const float* __restrict__ wv,
    const float* __restrict__ uqw, const float* __restrict__ ukw, const float* __restrict__ uvw) {
    extern __shared__ float sm[];
    float* xs   = sm;                 // 64 x 68
    float* uo   = xs + 64 * 68;       // 3 x (64 x 68)
    float* wbig = uo + 3 * 64 * 68;   // 64 x 260

    const int t = threadIdx.x;
    const int row0 = blockIdx.x * 64;
    const int b    = row0 >> 11;
    const int lr0  = row0 & (SEQ - 1);

    for (int i = t; i < 64 * 16; i += 256) {
        int r = i >> 4, c = (i & 15) * 4;
        *(float4*)(xs + r * 68 + c)              = *(const float4*)(x + (size_t)(row0 + r) * DM + c);
        *(float4*)(wbig + 0 * 4352 + r * 68 + c) = *(const float4*)(uqw + r * 64 + c);
        *(float4*)(wbig + 1 * 4352 + r * 68 + c) = *(const float4*)(ukw + r * 64 + c);
        *(float4*)(wbig + 2 * 4352 + r * 68 + c) = *(const float4*)(uvw + r * 64 + c);
    }
    __syncthreads();

    const int rg = t >> 5;
    const int cg = t & 31;

    if (cg < 24) {
        const int mat = cg >> 3;
        const int c0 = (cg & 7) * 8;
        const float* w = wbig + mat * 4352;
        float acc[8][8];
        #pragma unroll
        for (int i = 0; i < 8; ++i)
            #pragma unroll
            for (int j = 0; j < 8; ++j) acc[i][j] = 0.f;
        for (int k = 0; k < 64; ++k) {
            float av[8];
            #pragma unroll
            for (int i = 0; i < 8; ++i) av[i] = xs[(rg * 8 + i) * 68 + k];
            float4 b0 = *(const float4*)(w + k * 68 + c0);
            float4 b1 = *(const float4*)(w + k * 68 + c0 + 4);
            float bv[8] = {b0.x, b0.y, b0.z, b0.w, b1.x, b1.y, b1.z, b1.w};
            #pragma unroll
            for (int i = 0; i < 8; ++i)
                #pragma unroll
                for (int j = 0; j < 8; ++j) acc[i][j] += av[i] * bv[j];
        }
        float* dst = uo + mat * 4352;
        #pragma unroll
        for (int i = 0; i < 8; ++i)
            #pragma unroll
            for (int j = 0; j < 8; ++j)
                dst[(rg * 8 + i) * 68 + c0 + j] = acc[i][j];
    }
    __syncthreads();

    const float gq = g_gates[b] * 0.125f;
    const float gk = g_gates[8 + b];
    const float gv = g_gates[16 + b];

    for (int i = t; i < 64 * 64; i += 256) {
        int r = i >> 6, j = i & 63;
        float vq = tf32r(uo[r * 68 + j] * gq);
        float vk = tf32r(uo[4352 + r * 68 + j] * gk);
        size_t l = lr0 + r;
        #pragma unroll
        for (int h = 0; h < 4; ++h) {
            size_t base = (((size_t)b * 4 + h) * SEQ + l) * 128 + 64 + j;
            g_Qe[base] = vq;
            g_Ke[base] = vk;
        }
    }

    for (int m = 0; m < 3; ++m) {
        const float* w = (m == 0) ? wq : (m == 1) ? wk : wv;
        __syncthreads();
        for (int i = t; i < 64 * 64; i += 256) {
            int r = i >> 6, c = (i & 63) * 4;
            *(float4*)(wbig + r * 260 + c) = *(const float4*)(w + r * 256 + c);
        }
        __syncthreads();

        float acc[8][8];
        #pragma unroll
        for (int i = 0; i < 8; ++i)
            #pragma unroll
            for (int j = 0; j < 8; ++j) acc[i][j] = 0.f;
        for (int k = 0; k < 64; ++k) {
            float av[8];
            #pragma unroll
            for (int i = 0; i < 8; ++i) av[i] = xs[(rg * 8 + i) * 68 + k];
            float4 b0 = *(const float4*)(wbig + k * 260 + cg * 8);
            float4 b1 = *(const float4*)(wbig + k * 260 + cg * 8 + 4);
            float bv[8] = {b0.x, b0.y, b0.z, b0.w, b1.x, b1.y, b1.z, b1.w};
            #pragma unroll
            for (int i = 0; i < 8; ++i)
                #pragma unroll
                for (int j = 0; j < 8; ++j) acc[i][j] += av[i] * bv[j];
        }

        const int c0 = cg * 8;
        const int h  = c0 >> 6;
        const int j0 = c0 & 63;
        if (m == 2) {
            #pragma unroll
            for (int i = 0; i < 8; ++i) {
                size_t l = lr0 + rg * 8 + i;
                size_t base = (((size_t)b * 4 + h) * SEQ + l) * 64 + j0;
                #pragma unroll
                for (int j = 0; j < 8; ++j)
                    g_Ve[base + j] = acc[i][j] + uo[2 * 4352 + (rg * 8 + i) * 68 + j0 + j] * gv;
            }
        } else {
            float* tgt = (m == 0) ? g_Qe : g_Ke;
            float s = (m == 0) ? 0.125f : 1.0f;
            #pragma unroll
            for (int i = 0; i < 8; ++i) {
                size_t l = lr0 + rg * 8 + i;
                size_t base = (((size_t)b * 4 + h) * SEQ + l) * 128 + j0;
                #pragma unroll
                for (int j = 0; j < 8; ++j)
                    tgt[base + j] = tf32r(acc[i][j] * s);
            }
        }
    }
}

// ---------------------------------------------------------------------------
// Kernel 2: attention. One CTA = (b,h, 16 q-rows). Full 2048-k score row in
// smem, fused exp/mask + PV via tf32 mma, single normalized write-out.
// ---------------------------------------------------------------------------
#define ATT_SMEM_BYTES ((16*SSTR + 16*132 + 64*132 + 64*72 + 128 + 16 + 256) * 4)

__global__ void __launch_bounds__(256) attn_kernel(const void* __restrict__ mask,
                                                   float* __restrict__ attn_out) {
    extern __shared__ float sm[];
    float* Ss  = sm;                       // 16 x 2052
    float* qs  = Ss + 16 * SSTR;           // 16 x 132
    float* ks  = qs + 16 * 132;            // 64 x 132
    float* vs  = ks + 64 * 132;            // 64 x 72
    float* red = vs + 64 * 72;             // 8 x 16
    float* inv = red + 128;                // 16
    unsigned* ms = (unsigned*)(inv + 16);  // 16 rows x 16 u32 (64 mask bytes/row)

    const int t    = threadIdx.x;
    const int w    = t >> 5;
    const int lane = t & 31;
    const int g    = lane >> 2;
    const int tig  = lane & 3;

    const int bh = blockIdx.x >> 7;
    const int qt = blockIdx.x & 127;
    const int b  = bh >> 2;
    const int q0 = qt * 16;

    const int mmode = g_mask_mode;
    const float* Qg = g_Qe + ((size_t)bh * SEQ + q0) * 128;
    const float* Kg = g_Ke + (size_t)bh * SEQ * 128;
    const float* Vg = g_Ve + (size_t)bh * SEQ * 64;
    const unsigned char* mk8 = (const unsigned char*)mask + ((size_t)b * SEQ + q0) * SEQ;
    const int*           mk32 = (const int*)mask + ((size_t)b * SEQ + q0) * SEQ;

    for (int i = t; i < 16 * 32; i += 256) {
        int r = i >> 5, c = (i & 31) * 4;
        *(float4*)(qs + r * 132 + c) = *(const float4*)(Qg + (size_t)r * 128 + c);
    }
    __syncthreads();

    unsigned a[16][4];
    #pragma unroll
    for (int kk = 0; kk < 16; ++kk) {
        a[kk][0] = __float_as_uint(qs[g * 132 + kk * 8 + tig]);
        a[kk][1] = __float_as_uint(qs[(g + 8) * 132 + kk * 8 + tig]);
        a[kk][2] = __float_as_uint(qs[g * 132 + kk * 8 + tig + 4]);
        a[kk][3] = __float_as_uint(qs[(g + 8) * 132 + kk * 8 + tig + 4]);
    }

    float ctx0 = 0.f, ctx1 = 0.f, ctx2 = 0.f, ctx3 = 0.f;
    float sl0 = 0.f, sl1 = 0.f;
    const int n0 = w * 8;

    for (int k0 = 0; k0 < SEQ; k0 += 64) {
        for (int i = t; i < 64 * 32; i += 256) {
            int r = i >> 5, c = (i & 31) * 4;
            *(float4*)(ks + r * 132 + c) = *(const float4*)(Kg + (size_t)(k0 + r) * 128 + c);
        }
        for (int i = t; i < 64 * 16; i += 256) {
            int r = i >> 4, c = (i & 15) * 4;
            *(float4*)(vs + r * 72 + c) = *(const float4*)(Vg + (size_t)(k0 + r) * 64 + c);
        }
        {
            int r = t >> 4, c = t & 15;
            if (mmode) {
                int4 v = *(const int4*)(mk32 + (size_t)r * SEQ + k0 + c * 4);
                ms[r * 16 + c] = (v.x ? 1u : 0u) | (v.y ? 1u << 8 : 0u) |
                                 (v.z ? 1u << 16 : 0u) | (v.w ? 1u << 24 : 0u);
            } else {
                ms[r * 16 + c] = *(const unsigned*)(mk8 + (size_t)r * SEQ + k0 + c * 4);
            }
        }
        __syncthreads();

        float c0 = 0.f, c1 = 0.f, c2 = 0.f, c3 = 0.f;
        #pragma unroll
        for (int kk = 0; kk < 16; ++kk) {
            unsigned b0 = __float_as_uint(ks[(n0 + g) * 132 + kk * 8 + tig]);
            unsigned b1 = __float_as_uint(ks[(n0 + g) * 132 + kk * 8 + tig + 4]);
            mma_tf32(c0, c1, c2, c3, a[kk][0], a[kk][1], a[kk][2], a[kk][3], b0, b1);
        }
        {
            const unsigned char* msb = (const unsigned char*)ms;
            int col = n0 + 2 * tig;
            float p00 = msb[g * 64 + col]           ? 0.f : __expf(c0);
            float p01 = msb[g * 64 + col + 1]       ? 0.f : __expf(c1);
            float p10 = msb[(g + 8) * 64 + col]     ? 0.f : __expf(c2);
            float p11 = msb[(g + 8) * 64 + col + 1] ? 0.f : __expf(c3);
            sl0 += p00 + p01;
            sl1 += p10 + p11;
            *(float2*)(Ss + g * SSTR + k0 + col)       = make_float2(p00, p01);
            *(float2*)(Ss + (g + 8) * SSTR + k0 + col) = make_float2(p10, p11);
        }
        __syncthreads();

        #pragma unroll
        for (int kk = 0; kk < 8; ++kk) {
            unsigned pa0 = __float_as_uint(Ss[g * SSTR + k0 + kk * 8 + tig]);
            unsigned pa1 = __float_as_uint(Ss[(g + 8) * SSTR + k0 + kk * 8 + tig]);
            unsigned pa2 = __float_as_uint(Ss[g * SSTR + k0 + kk * 8 + tig + 4]);
            unsigned pa3 = __float_as_uint(Ss[(g + 8) * SSTR + k0 + kk * 8 + tig + 4]);
            unsigned vb0 = __float_as_uint(vs[(kk * 8 + tig) * 72 + n0 + g]);
            unsigned vb1 = __float_as_uint(vs[(kk * 8 + tig + 4) * 72 + n0 + g]);
            mma_tf32(ctx0, ctx1, ctx2, ctx3, pa0, pa1, pa2, pa3, vb0, vb1);
        }
        __syncthreads();
    }

    sl0 += __shfl_xor_sync(0xffffffffu, sl0, 1);
    sl0 += __shfl_xor_sync(0xffffffffu, sl0, 2);
    sl1 += __shfl_xor_sync(0xffffffffu, sl1, 1);
    sl1 += __shfl_xor_sync(0xffffffffu, sl1, 2);
    if (tig == 0) {
        red[w * 16 + g]     = sl0;
        red[w * 16 + g + 8] = sl1;
    }
    __syncthreads();
    if (t < 16) {
        float s = 0.f;
        #pragma unroll
        for (int ww = 0; ww < 8; ++ww) s += red[ww * 16 + t];
        inv[t] = 1.f / s;
    }
    __syncthreads();

    {
        float* ao = attn_out + ((size_t)bh * SEQ + q0) * SEQ;
        int r = t >> 4, c = t & 15;
        float iv = inv[r];
        for (int i = 0; i < 32; ++i) {
            float4 v = *(float4*)(Ss + r * SSTR + c * 4 + i * 64);
            v.x *= iv; v.y *= iv; v.z *= iv; v.w *= iv;
            *(float4*)(ao + (size_t)r * SEQ + c * 4 + i * 64) = v;
        }
    }
    {
        int h = bh & 3;
        int col = n0 + 2 * tig;
        float iv0 = inv[g], iv1 = inv[g + 8];
        size_t rbase = (size_t)b * SEQ + q0;
        *(float2*)(g_ctx + (rbase + g) * 256 + h * 64 + col)     = make_float2(ctx0 * iv0, ctx1 * iv0);
        *(float2*)(g_ctx + (rbase + g + 8) * 256 + h * 64 + col) = make_float2(ctx2 * iv1, ctx3 * iv1);
    }
}

// ---------------------------------------------------------------------------
// Kernel 3: fc + LN1 + FFN + LN2.  64 rows per CTA, 256 threads (4x4 tiles).
// ---------------------------------------------------------------------------
#define POST_SMEM_BYTES ((64*260 + 256*68 + 4*64*68) * 4)

__global__ void __launch_bounds__(256) post_kernel(
    const float* __restrict__ x, const float* __restrict__ fcw,
    const float* __restrict__ ln1g, const float* __restrict__ ln1b,
    const float* __restrict__ f1, const float* __restrict__ f2,
    const float* __restrict__ ln2g, const float* __restrict__ ln2b,
    float* __restrict__ res) {
    extern __shared__ float sm[];
    float* cs  = sm;                 // 64 x 260
    float* fs  = cs + 64 * 260;      // 256 x 68
    float* hs  = fs + 256 * 68;      // 64 x 68
    float* es  = hs + 64 * 68;       // 64 x 68
    float* f1s = es + 64 * 68;       // 64 x 68
    float* f2s = f1s + 64 * 68;      // 64 x 68

    const int t = threadIdx.x;
    const int row0 = blockIdx.x * 64;

    for (int i = t; i < 64 * 64; i += 256) {
        int r = i >> 6, c = (i & 63) * 4;
        *(float4*)(cs + r * 260 + c) = *(const float4*)(g_ctx + (size_t)(row0 + r) * 256 + c);
    }
    for (int i = t; i < 256 * 16; i += 256) {
        int r = i >> 4, c = (i & 15) * 4;
        *(float4*)(fs + r * 68 + c) = *(const float4*)(fcw + r * 64 + c);
    }
    for (int i = t; i < 64 * 16; i += 256) {
        int r = i >> 4, c = (i & 15) * 4;
        *(float4*)(hs + r * 68 + c)  = *(const float4*)(x + (size_t)(row0 + r) * DM + c);
        *(float4*)(f1s + r * 68 + c) = *(const float4*)(f1 + r * 64 + c);
        *(float4*)(f2s + r * 68 + c) = *(const float4*)(f2 + r * 64 + c);
    }
    __syncthreads();

    const int rg = t >> 4;
    const int cg = t & 15;

    float acc[4][4];
    #pragma unroll
    for (int i = 0; i < 4; ++i)
        #pragma unroll
        for (int j = 0; j < 4; ++j) acc[i][j] = 0.f;
    for (int k = 0; k < 256; ++k) {
        float av[4];
        #pragma unroll
        for (int i = 0; i < 4; ++i) av[i] = cs[(rg * 4 + i) * 260 + k];
        float4 bb = *(const float4*)(fs + k * 68 + cg * 4);
        float bv[4] = {bb.x, bb.y, bb.z, bb.w};
        #pragma unroll
        for (int i = 0; i < 4; ++i)
            #pragma unroll
            for (int j = 0; j < 4; ++j) acc[i][j] += av[i] * bv[j];
    }

    #pragma unroll
    for (int i = 0; i < 4; ++i) {
        float y[4];
        #pragma unroll
        for (int j = 0; j < 4; ++j) y[j] = acc[i][j] + hs[(rg * 4 + i) * 68 + cg * 4 + j];
        float s = y[0] + y[1] + y[2] + y[3];
        float q = y[0]*y[0] + y[1]*y[1] + y[2]*y[2] + y[3]*y[3];
        #pragma unroll
        for (int o = 1; o < 16; o <<= 1) {
            s += __shfl_xor_sync(0xffffffffu, s, o);
            q += __shfl_xor_sync(0xffffffffu, q, o);
        }
        float mu = s * (1.f / 64.f);
        float var = q * (1.f / 64.f) - mu * mu;
        float rs = rsqrtf(var + 1e-5f);
        #pragma unroll
        for (int j = 0; j < 4; ++j) {
            int c = cg * 4 + j;
            es[(rg * 4 + i) * 68 + c] = (y[j] - mu) * rs * ln1g[c] + ln1b[c];
        }
    }
    __syncthreads();

    float h4[4][4];
    #pragma unroll
    for (int i = 0; i < 4; ++i)
        #pragma unroll
        for (int j = 0; j < 4; ++j) h4[i][j] = 0.f;
    for (int k = 0; k < 64; ++k) {
        float av[4];
        #pragma unroll
        for (int i = 0; i < 4; ++i) av[i] = es[(rg * 4 + i) * 68 + k];
        float4 bb = *(const float4*)(f1s + k * 68 + cg * 4);
        float bv[4] = {bb.x, bb.y, bb.z, bb.w};
        #pragma unroll
        for (int i = 0; i < 4; ++i)
            #pragma unroll
            for (int j = 0; j < 4; ++j) h4[i][j] += av[i] * bv[j];
    }
    #pragma unroll
    for (int i = 0; i < 4; ++i)
        #pragma unroll
        for (int j = 0; j < 4; ++j)
            hs[(rg * 4 + i) * 68 + cg * 4 + j] = fmaxf(h4[i][j], 0.f);
    __syncthreads();

    float fa[4][4];
    #pragma unroll
    for (int i = 0; i < 4; ++i)
        #pragma unroll
        for (int j = 0; j < 4; ++j) fa[i][j] = 0.f;
    for (int k = 0; k < 64; ++k) {
        float av[4];
        #pragma unroll
        for (int i = 0; i < 4; ++i) av[i] = hs[(rg * 4 + i) * 68 + k];
        float4 bb = *(const float4*)(f2s + k * 68 + cg * 4);
        float bv[4] = {bb.x, bb.y, bb.z, bb.w};
        #pragma unroll
        for (int i = 0; i < 4; ++i)
            #pragma unroll
            for (int j = 0; j < 4; ++j) fa[i][j] += av[i] * bv[j];
    }
    #pragma unroll
    for (int i = 0; i < 4; ++i) {
        float y[4];
        #pragma unroll
        for (int j = 0; j < 4; ++j) y[j] = fa[i][j] + es[(rg * 4 + i) * 68 + cg * 4 + j];
        float s = y[0] + y[1] + y[2] + y[3];
        float q = y[0]*y[0] + y[1]*y[1] + y[2]*y[2] + y[3]*y[3];
        #pragma unroll
        for (int o = 1; o < 16; o <<= 1) {
            s += __shfl_xor_sync(0xffffffffu, s, o);
            q += __shfl_xor_sync(0xffffffffu, q, o);
        }
        float mu = s * (1.f / 64.f);
        float var = q * (1.f / 64.f) - mu * mu;
        float rs = rsqrtf(var + 1e-5f);
        float4 o4;
        o4.x = (y[0] - mu) * rs * ln2g[cg * 4 + 0] + ln2b[cg * 4 + 0];
        o4.y = (y[1] - mu) * rs * ln2g[cg * 4 + 1] + ln2b[cg * 4 + 1];
        o4.z = (y[2] - mu) * rs * ln2g[cg * 4 + 2] + ln2b[cg * 4 + 2];
        o4.w = (y[3] - mu) * rs * ln2g[cg * 4 + 3] + ln2b[cg * 4 + 3];
        *(float4*)(res + (size_t)(row0 + rg * 4 + i) * 64 + cg * 4) = o4;
    }
}

// ---------------------------------------------------------------------------
// Launch
// ---------------------------------------------------------------------------
extern "C" void kernel_launch(void* const* d_in, const int* in_sizes, int n_in,
                              void* d_out, int out_size) {
    const float* x    = (const float*)d_in[0];
    const void*  mask = d_in[1];
    const float* u    = (const float*)d_in[2];
    const float* wq   = (const float*)d_in[3];
    const float* wk   = (const float*)d_in[4];
    const float* wv   = (const float*)d_in[5];
    const float* uqw  = (const float*)d_in[6];
    const float* ukw  = (const float*)d_in[7];
    const float* uvw  = (const float*)d_in[8];
    const float* sq1  = (const float*)d_in[9];
    const float* sq2  = (const float*)d_in[10];
    const float* sk1  = (const float*)d_in[11];
    const float* sk2  = (const float*)d_in[12];
    const float* sv1  = (const float*)d_in[13];
    const float* sv2  = (const float*)d_in[14];
    const float* fcw  = (const float*)d_in[15];
    const float* ln1g = (const float*)d_in[16];
    const float* ln1b = (const float*)d_in[17];
    const float* ffn1 = (const float*)d_in[18];
    const float* ffn2 = (const float*)d_in[19];
    const float* ln2g = (const float*)d_in[20];
    const float* ln2b = (const float*)d_in[21];

    float* res  = (float*)d_out;
    float* attn = res + (size_t)NB * SEQ * DM;

    cudaFuncSetAttribute(proj_kernel, cudaFuncAttributeMaxDynamicSharedMemorySize, PROJ_SMEM_BYTES);
    cudaFuncSetAttribute(attn_kernel, cudaFuncAttributeMaxDynamicSharedMemorySize, ATT_SMEM_BYTES);
    cudaFuncSetAttribute(post_kernel, cudaFuncAttributeMaxDynamicSharedMemorySize, POST_SMEM_BYTES);

    detect_mask_kernel<<<1, 32>>>((const unsigned char*)mask);
    gates_kernel<<<NB, 32>>>(u, sq1, sq2, sk1, sk2, sv1, sv2);
    proj_kernel<<<(NB * SEQ) / 64, 256, PROJ_SMEM_BYTES>>>(x, wq, wk, wv, uqw, ukw, uvw);
    attn_kernel<<<NB * NH * (SEQ / 16), 256, ATT_SMEM_BYTES>>>(mask, attn);
    post_kernel<<<(NB * SEQ) / 64, 256, POST_SMEM_BYTES>>>(x, fcw, ln1g, ln1b, ffn1, ffn2,
                                                           ln2g, ln2b, res);
}

// round 5
// speedup vs baseline: 2.3482x; 2.3482x over previous
#include <cuda_runtime.h>
#include <cstdint>
#include <cstddef>

// ---------------------------------------------------------------------------
// Problem constants
// ---------------------------------------------------------------------------
#define NB   8
#define NH   4
#define SEQ  2048
#define DM   64

// attention tiling
#define TQ   32          // q rows per CTA
#define KSTR 132         // K tile row stride (floats)
#define VSTR 72
#define PSTR 68

// ---------------------------------------------------------------------------
// Static device scratch
// ---------------------------------------------------------------------------
__device__ float    g_gates[3 * NB];
__device__ int      g_mask_mode;                           // 1 = int32 mask, 0 = byte mask
__device__ float    g_Qe[(size_t)NB * NH * SEQ * 128];     // 33.5 MB
__device__ float    g_Ke[(size_t)NB * NH * SEQ * 128];     // 33.5 MB
__device__ float    g_Ve[(size_t)NB * NH * SEQ * 64];      // 16.8 MB
__device__ float    g_ctx[(size_t)NB * SEQ * 256];         // 16.8 MB
__device__ unsigned g_maskb[(size_t)NB * SEQ * 64];        // 4 MB  (bit-packed mask)
__device__ float    g_inv[(size_t)NB * NH * SEQ];          // per-row 1/sum

// ---------------------------------------------------------------------------
// Helpers
// ---------------------------------------------------------------------------
__device__ __forceinline__ float tf32r(float x) {
    float y;
    asm("cvt.rna.tf32.f32 %0, %1;" : "=f"(y) : "f"(x));
    return y;
}

__device__ __forceinline__ void mma_tf32(float& c0, float& c1, float& c2, float& c3,
                                         unsigned a0, unsigned a1, unsigned a2, unsigned a3,
                                         unsigned b0, unsigned b1) {
    asm volatile(
        "mma.sync.aligned.m16n8k8.row.col.f32.tf32.tf32.f32 "
        "{%0,%1,%2,%3},{%4,%5,%6,%7},{%8,%9},{%0,%1,%2,%3};"
        : "+f"(c0), "+f"(c1), "+f"(c2), "+f"(c3)
        : "r"(a0), "r"(a1), "r"(a2), "r"(a3), "r"(b0), "r"(b1));
}

__device__ __forceinline__ void cp_async16(void* smem, const void* gmem) {
    unsigned sa = (unsigned)__cvta_generic_to_shared(smem);
    asm volatile("cp.async.cg.shared.global [%0], [%1], 16;\n" :: "r"(sa), "l"(gmem));
}
__device__ __forceinline__ void cp_async4(void* smem, const void* gmem) {
    unsigned sa = (unsigned)__cvta_generic_to_shared(smem);
    asm volatile("cp.async.ca.shared.global [%0], [%1], 4;\n" :: "r"(sa), "l"(gmem));
}
#define CP_COMMIT() asm volatile("cp.async.commit_group;\n")
#define CP_WAIT(n)  asm volatile("cp.async.wait_group %0;\n" :: "n"(n))

// ---------------------------------------------------------------------------
// Kernel D: detect mask encoding (int32 vs byte)
// ---------------------------------------------------------------------------
__global__ void detect_mask_kernel(const unsigned char* __restrict__ m) {
    int found = 0;
    for (int i = threadIdx.x; i < 1024; i += 32)
        if (m[i * 4 + 1] | m[i * 4 + 2] | m[i * 4 + 3]) found = 1;
    for (int o = 16; o; o >>= 1)
        found |= __shfl_xor_sync(0xffffffffu, found, o);
    if (threadIdx.x == 0) g_mask_mode = found ? 0 : 1;
}

// ---------------------------------------------------------------------------
// Kernel M: bit-pack the mask. One thread per output u32 word.
// ---------------------------------------------------------------------------
__global__ void __launch_bounds__(256) convert_mask_kernel(const void* __restrict__ mask) {
    int idx = blockIdx.x * 256 + threadIdx.x;       // total NB*SEQ*64 = 1,048,576
    size_t base = (size_t)(idx >> 6) * SEQ + (size_t)(idx & 63) * 32;
    unsigned bits = 0;
    if (g_mask_mode) {
        const int* m = (const int*)mask + base;
        #pragma unroll
        for (int i = 0; i < 32; ++i) bits |= (m[i] ? 1u : 0u) << i;
    } else {
        const unsigned char* m = (const unsigned char*)mask + base;
        #pragma unroll
        for (int i = 0; i < 32; ++i) bits |= (m[i] ? 1u : 0u) << i;
    }
    g_maskb[idx] = bits;
}

// ---------------------------------------------------------------------------
// Kernel 0: scalar gates
// ---------------------------------------------------------------------------
__global__ void gates_kernel(const float* __restrict__ u,
                             const float* __restrict__ sq1, const float* __restrict__ sq2,
                             const float* __restrict__ sk1, const float* __restrict__ sk2,
                             const float* __restrict__ sv1, const float* __restrict__ sv2) {
    const int b = blockIdx.x;
    const int lane = threadIdx.x;
    float hq = 0.f, hk = 0.f, hv = 0.f;
    for (int d = 0; d < DM; ++d) {
        float uv = u[b * DM + d];
        hq += uv * sq1[d * 32 + lane];
        hk += uv * sk1[d * 32 + lane];
        hv += uv * sv1[d * 32 + lane];
    }
    hq = fmaxf(hq, 0.f) * sq2[lane];
    hk = fmaxf(hk, 0.f) * sk2[lane];
    hv = fmaxf(hv, 0.f) * sv2[lane];
    for (int off = 16; off; off >>= 1) {
        hq += __shfl_xor_sync(0xffffffffu, hq, off);
        hk += __shfl_xor_sync(0xffffffffu, hk, off);
        hv += __shfl_xor_sync(0xffffffffu, hv, off);
    }
    if (lane == 0) {
        g_gates[b]      = hq;
        g_gates[8 + b]  = hk;
        g_gates[16 + b] = hv;
    }
}

// ---------------------------------------------------------------------------
// Kernel 1: projections (unchanged from passing R4 version)
// ---------------------------------------------------------------------------
#define PROJ_SMEM_BYTES ((64*68 + 3*64*68 + 64*260) * 4)

__global__ void __launch_bounds__(256) proj_kernel(
    const float* __restrict__ x,
    const float* __restrict__ wq, const float* __restrict__ wk, const float* __restrict__ wv,
    const float* __restrict__ uqw, const float* __restrict__ ukw, const float* __restrict__ uvw) {
    extern __shared__ float sm[];
    float* xs   = sm;                 // 64 x 68
    float* uo   = xs + 64 * 68;       // 3 x (64 x 68)
    float* wbig = uo + 3 * 64 * 68;   // 64 x 260

    const int t = threadIdx.x;
    const int row0 = blockIdx.x * 64;
    const int b    = row0 >> 11;
    const int lr0  = row0 & (SEQ - 1);

    for (int i = t; i < 64 * 16; i += 256) {
        int r = i >> 4, c = (i & 15) * 4;
        *(float4*)(xs + r * 68 + c)              = *(const float4*)(x + (size_t)(row0 + r) * DM + c);
        *(float4*)(wbig + 0 * 4352 + r * 68 + c) = *(const float4*)(uqw + r * 64 + c);
        *(float4*)(wbig + 1 * 4352 + r * 68 + c) = *(const float4*)(ukw + r * 64 + c);
        *(float4*)(wbig + 2 * 4352 + r * 68 + c) = *(const float4*)(uvw + r * 64 + c);
    }
    __syncthreads();

    const int rg = t >> 5;
    const int cg = t & 31;

    if (cg < 24) {
        const int mat = cg >> 3;
        const int c0 = (cg & 7) * 8;
        const float* w = wbig + mat * 4352;
        float acc[8][8];
        #pragma unroll
        for (int i = 0; i < 8; ++i)
            #pragma unroll
            for (int j = 0; j < 8; ++j) acc[i][j] = 0.f;
        for (int k = 0; k < 64; ++k) {
            float av[8];
            #pragma unroll
            for (int i = 0; i < 8; ++i) av[i] = xs[(rg * 8 + i) * 68 + k];
            float4 b0 = *(const float4*)(w + k * 68 + c0);
            float4 b1 = *(const float4*)(w + k * 68 + c0 + 4);
            float bv[8] = {b0.x, b0.y, b0.z, b0.w, b1.x, b1.y, b1.z, b1.w};
            #pragma unroll
            for (int i = 0; i < 8; ++i)
                #pragma unroll
                for (int j = 0; j < 8; ++j) acc[i][j] += av[i] * bv[j];
        }
        float* dst = uo + mat * 4352;
        #pragma unroll
        for (int i = 0; i < 8; ++i)
            #pragma unroll
            for (int j = 0; j < 8; ++j)
                dst[(rg * 8 + i) * 68 + c0 + j] = acc[i][j];
    }
    __syncthreads();

    const float gq = g_gates[b] * 0.125f;
    const float gk = g_gates[8 + b];
    const float gv = g_gates[16 + b];

    for (int i = t; i < 64 * 64; i += 256) {
        int r = i >> 6, j = i & 63;
        float vq = tf32r(uo[r * 68 + j] * gq);
        float vk = tf32r(uo[4352 + r * 68 + j] * gk);
        size_t l = lr0 + r;
        #pragma unroll
        for (int h = 0; h < 4; ++h) {
            size_t base = (((size_t)b * 4 + h) * SEQ + l) * 128 + 64 + j;
            g_Qe[base] = vq;
            g_Ke[base] = vk;
        }
    }

    for (int m = 0; m < 3; ++m) {
        const float* w = (m == 0) ? wq : (m == 1) ? wk : wv;
        __syncthreads();
        for (int i = t; i < 64 * 64; i += 256) {
            int r = i >> 6, c = (i & 63) * 4;
            *(float4*)(wbig + r * 260 + c) = *(const float4*)(w + r * 256 + c);
        }
        __syncthreads();

        float acc[8][8];
        #pragma unroll
        for (int i = 0; i < 8; ++i)
            #pragma unroll
            for (int j = 0; j < 8; ++j) acc[i][j] = 0.f;
        for (int k = 0; k < 64; ++k) {
            float av[8];
            #pragma unroll
            for (int i = 0; i < 8; ++i) av[i] = xs[(rg * 8 + i) * 68 + k];
            float4 b0 = *(const float4*)(wbig + k * 260 + cg * 8);
            float4 b1 = *(const float4*)(wbig + k * 260 + cg * 8 + 4);
            float bv[8] = {b0.x, b0.y, b0.z, b0.w, b1.x, b1.y, b1.z, b1.w};
            #pragma unroll
            for (int i = 0; i < 8; ++i)
                #pragma unroll
                for (int j = 0; j < 8; ++j) acc[i][j] += av[i] * bv[j];
        }

        const int c0 = cg * 8;
        const int h  = c0 >> 6;
        const int j0 = c0 & 63;
        if (m == 2) {
            #pragma unroll
            for (int i = 0; i < 8; ++i) {
                size_t l = lr0 + rg * 8 + i;
                size_t base = (((size_t)b * 4 + h) * SEQ + l) * 64 + j0;
                #pragma unroll
                for (int j = 0; j < 8; ++j)
                    g_Ve[base + j] = acc[i][j] + uo[2 * 4352 + (rg * 8 + i) * 68 + j0 + j] * gv;
            }
        } else {
            float* tgt = (m == 0) ? g_Qe : g_Ke;
            float s = (m == 0) ? 0.125f : 1.0f;
            #pragma unroll
            for (int i = 0; i < 8; ++i) {
                size_t l = lr0 + rg * 8 + i;
                size_t base = (((size_t)b * 4 + h) * SEQ + l) * 128 + j0;
                #pragma unroll
                for (int j = 0; j < 8; ++j)
                    tgt[base + j] = tf32r(acc[i][j] * s);
            }
        }
    }
}

// ---------------------------------------------------------------------------
// Kernel 2 (v2): attention. CTA = (b,h, 32 q-rows), 512 threads / 16 warps.
// Double-buffered cp.async staging of K/V/mask-bits. Writes UNNORMALIZED p to
// attn_out, accumulates PV, stores per-row 1/sum to g_inv (+smem for ctx).
// Warp layout: qh = w>>3 selects 16-row q-half, n0 = (w&7)*8 selects k-cols.
// smem (floats): qs 32x132 | ks 2x64x132 | vs 2x64x72 | ps 32x68 | red 256 |
//                inv 32 | msb 2x64 (u32)
// ---------------------------------------------------------------------------
#define ATT_SMEM_FLOATS (TQ*KSTR + 2*64*KSTR + 2*64*VSTR + TQ*PSTR + 256 + 32 + 128)
#define ATT_SMEM_BYTES  (ATT_SMEM_FLOATS * 4)

__global__ void __launch_bounds__(512) attn2_kernel(float* __restrict__ attn_out) {
    extern __shared__ float sm[];
    float* qs  = sm;                       // 32 x 132
    float* ks  = qs + TQ * KSTR;           // 2 x 64 x 132
    float* vs  = ks + 2 * 64 * KSTR;       // 2 x 64 x 72
    float* ps  = vs + 2 * 64 * VSTR;       // 32 x 68
    float* red = ps + TQ * PSTR;           // 16 x 16
    float* inv = red + 256;                // 32
    unsigned* msb = (unsigned*)(inv + 32); // 2 x 64

    const int t    = threadIdx.x;
    const int w    = t >> 5;
    const int lane = t & 31;
    const int g    = lane >> 2;
    const int tig  = lane & 3;
    const int qh   = w >> 3;               // 0/1: q-half
    const int n0   = (w & 7) * 8;          // k-col group within tile

    const int bh = blockIdx.x >> 6;        // 64 q-tiles per (b,h)
    const int qt = blockIdx.x & 63;
    const int b  = bh >> 2;
    const int h  = bh & 3;
    const int q0 = qt * TQ;

    const float* Qg = g_Qe + ((size_t)bh * SEQ + q0) * 128;
    const float* Kg = g_Ke + (size_t)bh * SEQ * 128;
    const float* Vg = g_Ve + (size_t)bh * SEQ * 64;
    const unsigned* Mb = g_maskb + ((size_t)b * SEQ + q0) * 64;
    float* ao = attn_out + ((size_t)bh * SEQ + q0) * SEQ;

    // ---- stage Q + tile 0 (group 0) ----
    for (int i = t; i < TQ * 32; i += 512) {
        int r = i >> 5, c = (i & 31) * 4;
        cp_async16(qs + r * KSTR + c, Qg + (size_t)r * 128 + c);
    }
    for (int i = t; i < 64 * 32; i += 512) {
        int r = i >> 5, c = (i & 31) * 4;
        cp_async16(ks + r * KSTR + c, Kg + (size_t)r * 128 + c);
    }
    for (int i = t; i < 64 * 16; i += 512) {
        int r = i >> 4, c = (i & 15) * 4;
        cp_async16(vs + r * VSTR + c, Vg + (size_t)r * 64 + c);
    }
    if (t < 64)
        cp_async4(msb + t, Mb + (size_t)(t >> 1) * 64 + (t & 1));
    CP_COMMIT();
    CP_WAIT(0);
    __syncthreads();

    // ---- hoist A (Q) fragments: invariant over k-tiles ----
    unsigned a[16][4];
    #pragma unroll
    for (int kk = 0; kk < 16; ++kk) {
        a[kk][0] = __float_as_uint(qs[(qh * 16 + g)     * KSTR + kk * 8 + tig]);
        a[kk][1] = __float_as_uint(qs[(qh * 16 + 8 + g) * KSTR + kk * 8 + tig]);
        a[kk][2] = __float_as_uint(qs[(qh * 16 + g)     * KSTR + kk * 8 + tig + 4]);
        a[kk][3] = __float_as_uint(qs[(qh * 16 + 8 + g) * KSTR + kk * 8 + tig + 4]);
    }

    float ctx0 = 0.f, ctx1 = 0.f, ctx2 = 0.f, ctx3 = 0.f;
    float sl0 = 0.f, sl1 = 0.f;

    for (int tile = 0; tile < SEQ / 64; ++tile) {
        const int buf = tile & 1;
        // prefetch tile+1 into the other buffer (freed by last tile's end sync)
        if (tile + 1 < SEQ / 64) {
            const int nb = buf ^ 1;
            const int nk0 = (tile + 1) * 64;
            for (int i = t; i < 64 * 32; i += 512) {
                int r = i >> 5, c = (i & 31) * 4;
                cp_async16(ks + nb * 64 * KSTR + r * KSTR + c,
                           Kg + (size_t)(nk0 + r) * 128 + c);
            }
            for (int i = t; i < 64 * 16; i += 512) {
                int r = i >> 4, c = (i & 15) * 4;
                cp_async16(vs + nb * 64 * VSTR + r * VSTR + c,
                           Vg + (size_t)(nk0 + r) * 64 + c);
            }
            if (t < 64)
                cp_async4(msb + nb * 64 + t,
                          Mb + (size_t)(t >> 1) * 64 + (nk0 >> 5) + (t & 1));
            CP_COMMIT();
            CP_WAIT(1);      // current tile's group complete; next still in flight
        } else {
            CP_WAIT(0);
        }
        __syncthreads();

        const float* kb = ks + buf * 64 * KSTR;
        const float* vb = vs + buf * 64 * VSTR;
        const unsigned* mb = msb + buf * 64;
        const int k0 = tile * 64;

        // ---- QK scores for this warp's 16x8 tile ----
        float c0 = 0.f, c1 = 0.f, c2 = 0.f, c3 = 0.f;
        #pragma unroll
        for (int kk = 0; kk < 16; ++kk) {
            unsigned b0 = __float_as_uint(kb[(n0 + g) * KSTR + kk * 8 + tig]);
            unsigned b1 = __float_as_uint(kb[(n0 + g) * KSTR + kk * 8 + tig + 4]);
            mma_tf32(c0, c1, c2, c3, a[kk][0], a[kk][1], a[kk][2], a[kk][3], b0, b1);
        }

        // ---- mask + exp -> p (unnormalized), accumulate sums ----
        {
            const int col = n0 + 2 * tig;               // even
            unsigned w0 = mb[(qh * 16 + g) * 2 + (col >> 5)];
            unsigned w1 = mb[(qh * 16 + 8 + g) * 2 + (col >> 5)];
            float p00 = ((w0 >> (col & 31)) & 1u)       ? 0.f : __expf(c0);
            float p01 = ((w0 >> ((col + 1) & 31)) & 1u) ? 0.f : __expf(c1);
            float p10 = ((w1 >> (col & 31)) & 1u)       ? 0.f : __expf(c2);
            float p11 = ((w1 >> ((col + 1) & 31)) & 1u) ? 0.f : __expf(c3);
            sl0 += p00 + p01;
            sl1 += p10 + p11;
            *(float2*)(ps + (qh * 16 + g)     * PSTR + col) = make_float2(p00, p01);
            *(float2*)(ps + (qh * 16 + 8 + g) * PSTR + col) = make_float2(p10, p11);
        }
        __syncthreads();

        // ---- write unnormalized p tile to global (coalesced) ----
        {
            int r = t >> 4, c4 = (t & 15) * 4;
            *(float4*)(ao + (size_t)r * SEQ + k0 + c4) = *(float4*)(ps + r * PSTR + c4);
        }

        // ---- PV accumulate: ctx[16 x 8] per warp ----
        #pragma unroll
        for (int kk = 0; kk < 8; ++kk) {
            unsigned pa0 = __float_as_uint(ps[(qh * 16 + g)     * PSTR + kk * 8 + tig]);
            unsigned pa1 = __float_as_uint(ps[(qh * 16 + 8 + g) * PSTR + kk * 8 + tig]);
            unsigned pa2 = __float_as_uint(ps[(qh * 16 + g)     * PSTR + kk * 8 + tig + 4]);
            unsigned pa3 = __float_as_uint(ps[(qh * 16 + 8 + g) * PSTR + kk * 8 + tig + 4]);
            unsigned vb0 = __float_as_uint(vb[(kk * 8 + tig)     * VSTR + n0 + g]);
            unsigned vb1 = __float_as_uint(vb[(kk * 8 + tig + 4) * VSTR + n0 + g]);
            mma_tf32(ctx0, ctx1, ctx2, ctx3, pa0, pa1, pa2, pa3, vb0, vb1);
        }
        // next iteration's top __syncthreads orders ps overwrite after these reads
    }
    __syncthreads();

    // ---- row-sum reduction across n-warps ----
    sl0 += __shfl_xor_sync(0xffffffffu, sl0, 1);
    sl0 += __shfl_xor_sync(0xffffffffu, sl0, 2);
    sl1 += __shfl_xor_sync(0xffffffffu, sl1, 1);
    sl1 += __shfl_xor_sync(0xffffffffu, sl1, 2);
    if (tig == 0) {
        red[w * 16 + g]     = sl0;   // row qh*16 + g
        red[w * 16 + 8 + g] = sl1;   // row qh*16 + 8 + g
    }
    __syncthreads();
    if (t < 32) {
        int wb = (t >= 16) ? 8 : 0;
        int rr = t & 15;
        float s = 0.f;
        #pragma unroll
        for (int ww = 0; ww < 8; ++ww) s += red[(wb + ww) * 16 + rr];
        float iv = 1.f / s;
        inv[t] = iv;
        g_inv[(size_t)bh * SEQ + q0 + t] = iv;
    }
    __syncthreads();

    // ---- normalized ctx write ----
    {
        const int col = n0 + 2 * tig;
        float iv0 = inv[qh * 16 + g];
        float iv1 = inv[qh * 16 + 8 + g];
        size_t r0 = (size_t)b * SEQ + q0 + qh * 16;
        *(float2*)(g_ctx + (r0 + g)     * 256 + h * 64 + col) = make_float2(ctx0 * iv0, ctx1 * iv0);
        *(float2*)(g_ctx + (r0 + 8 + g) * 256 + h * 64 + col) = make_float2(ctx2 * iv1, ctx3 * iv1);
    }
}

// ---------------------------------------------------------------------------
// Kernel 2b: normalize attn rows in place. One block per row.
// ---------------------------------------------------------------------------
__global__ void __launch_bounds__(128) norm_kernel(float* __restrict__ attn) {
    const size_t row = blockIdx.x;
    const float iv = g_inv[row];
    float4* p = (float4*)(attn + row * SEQ);
    #pragma unroll
    for (int i = threadIdx.x; i < SEQ / 4; i += 128) {
        float4 v = p[i];
        v.x *= iv; v.y *= iv; v.z *= iv; v.w *= iv;
        p[i] = v;
    }
}

// ---------------------------------------------------------------------------
// Kernel 3: fc + LN1 + FFN + LN2 (unchanged from passing R4 version)
// ---------------------------------------------------------------------------
#define POST_SMEM_BYTES ((64*260 + 256*68 + 4*64*68) * 4)

__global__ void __launch_bounds__(256) post_kernel(
    const float* __restrict__ x, const float* __restrict__ fcw,
    const float* __restrict__ ln1g, const float* __restrict__ ln1b,
    const float* __restrict__ f1, const float* __restrict__ f2,
    const float* __restrict__ ln2g, const float* __restrict__ ln2b,
    float* __restrict__ res) {
    extern __shared__ float sm[];
    float* cs  = sm;                 // 64 x 260
    float* fs  = cs + 64 * 260;      // 256 x 68
    float* hs  = fs + 256 * 68;      // 64 x 68
    float* es  = hs + 64 * 68;       // 64 x 68
    float* f1s = es + 64 * 68;       // 64 x 68
    float* f2s = f1s + 64 * 68;      // 64 x 68

    const int t = threadIdx.x;
    const int row0 = blockIdx.x * 64;

    for (int i = t; i < 64 * 64; i += 256) {
        int r = i >> 6, c = (i & 63) * 4;
        *(float4*)(cs + r * 260 + c) = *(const float4*)(g_ctx + (size_t)(row0 + r) * 256 + c);
    }
    for (int i = t; i < 256 * 16; i += 256) {
        int r = i >> 4, c = (i & 15) * 4;
        *(float4*)(fs + r * 68 + c) = *(const float4*)(fcw + r * 64 + c);
    }
    for (int i = t; i < 64 * 16; i += 256) {
        int r = i >> 4, c = (i & 15) * 4;
        *(float4*)(hs + r * 68 + c)  = *(const float4*)(x + (size_t)(row0 + r) * DM + c);
        *(float4*)(f1s + r * 68 + c) = *(const float4*)(f1 + r * 64 + c);
        *(float4*)(f2s + r * 68 + c) = *(const float4*)(f2 + r * 64 + c);
    }
    __syncthreads();

    const int rg = t >> 4;
    const int cg = t & 15;

    float acc[4][4];
    #pragma unroll
    for (int i = 0; i < 4; ++i)
        #pragma unroll
        for (int j = 0; j < 4; ++j) acc[i][j] = 0.f;
    for (int k = 0; k < 256; ++k) {
        float av[4];
        #pragma unroll
        for (int i = 0; i < 4; ++i) av[i] = cs[(rg * 4 + i) * 260 + k];
        float4 bb = *(const float4*)(fs + k * 68 + cg * 4);
        float bv[4] = {bb.x, bb.y, bb.z, bb.w};
        #pragma unroll
        for (int i = 0; i < 4; ++i)
            #pragma unroll
            for (int j = 0; j < 4; ++j) acc[i][j] += av[i] * bv[j];
    }

    #pragma unroll
    for (int i = 0; i < 4; ++i) {
        float y[4];
        #pragma unroll
        for (int j = 0; j < 4; ++j) y[j] = acc[i][j] + hs[(rg * 4 + i) * 68 + cg * 4 + j];
        float s = y[0] + y[1] + y[2] + y[3];
        float q = y[0]*y[0] + y[1]*y[1] + y[2]*y[2] + y[3]*y[3];
        #pragma unroll
        for (int o = 1; o < 16; o <<= 1) {
            s += __shfl_xor_sync(0xffffffffu, s, o);
            q += __shfl_xor_sync(0xffffffffu, q, o);
        }
        float mu = s * (1.f / 64.f);
        float var = q * (1.f / 64.f) - mu * mu;
        float rs = rsqrtf(var + 1e-5f);
        #pragma unroll
        for (int j = 0; j < 4; ++j) {
            int c = cg * 4 + j;
            es[(rg * 4 + i) * 68 + c] = (y[j] - mu) * rs * ln1g[c] + ln1b[c];
        }
    }
    __syncthreads();

    float h4[4][4];
    #pragma unroll
    for (int i = 0; i < 4; ++i)
        #pragma unroll
        for (int j = 0; j < 4; ++j) h4[i][j] = 0.f;
    for (int k = 0; k < 64; ++k) {
        float av[4];
        #pragma unroll
        for (int i = 0; i < 4; ++i) av[i] = es[(rg * 4 + i) * 68 + k];
        float4 bb = *(const float4*)(f1s + k * 68 + cg * 4);
        float bv[4] = {bb.x, bb.y, bb.z, bb.w};
        #pragma unroll
        for (int i = 0; i < 4; ++i)
            #pragma unroll
            for (int j = 0; j < 4; ++j) h4[i][j] += av[i] * bv[j];
    }
    #pragma unroll
    for (int i = 0; i < 4; ++i)
        #pragma unroll
        for (int j = 0; j < 4; ++j)
            hs[(rg * 4 + i) * 68 + cg * 4 + j] = fmaxf(h4[i][j], 0.f);
    __syncthreads();

    float fa[4][4];
    #pragma unroll
    for (int i = 0; i < 4; ++i)
        #pragma unroll
        for (int j = 0; j < 4; ++j) fa[i][j] = 0.f;
    for (int k = 0; k < 64; ++k) {
        float av[4];
        #pragma unroll
        for (int i = 0; i < 4; ++i) av[i] = hs[(rg * 4 + i) * 68 + k];
        float4 bb = *(const float4*)(f2s + k * 68 + cg * 4);
        float bv[4] = {bb.x, bb.y, bb.z, bb.w};
        #pragma unroll
        for (int i = 0; i < 4; ++i)
            #pragma unroll
            for (int j = 0; j < 4; ++j) fa[i][j] += av[i] * bv[j];
    }
    #pragma unroll
    for (int i = 0; i < 4; ++i) {
        float y[4];
        #pragma unroll
        for (int j = 0; j < 4; ++j) y[j] = fa[i][j] + es[(rg * 4 + i) * 68 + cg * 4 + j];
        float s = y[0] + y[1] + y[2] + y[3];
        float q = y[0]*y[0] + y[1]*y[1] + y[2]*y[2] + y[3]*y[3];
        #pragma unroll
        for (int o = 1; o < 16; o <<= 1) {
            s += __shfl_xor_sync(0xffffffffu, s, o);
            q += __shfl_xor_sync(0xffffffffu, q, o);
        }
        float mu = s * (1.f / 64.f);
        float var = q * (1.f / 64.f) - mu * mu;
        float rs = rsqrtf(var + 1e-5f);
        float4 o4;
        o4.x = (y[0] - mu) * rs * ln2g[cg * 4 + 0] + ln2b[cg * 4 + 0];
        o4.y = (y[1] - mu) * rs * ln2g[cg * 4 + 1] + ln2b[cg * 4 + 1];
        o4.z = (y[2] - mu) * rs * ln2g[cg * 4 + 2] + ln2b[cg * 4 + 2];
        o4.w = (y[3] - mu) * rs * ln2g[cg * 4 + 3] + ln2b[cg * 4 + 3];
        *(float4*)(res + (size_t)(row0 + rg * 4 + i) * 64 + cg * 4) = o4;
    }
}

// ---------------------------------------------------------------------------
// Launch
// ---------------------------------------------------------------------------
extern "C" void kernel_launch(void* const* d_in, const int* in_sizes, int n_in,
                              void* d_out, int out_size) {
    const float* x    = (const float*)d_in[0];
    const void*  mask = d_in[1];
    const float* u    = (const float*)d_in[2];
    const float* wq   = (const float*)d_in[3];
    const float* wk   = (const float*)d_in[4];
    const float* wv   = (const float*)d_in[5];
    const float* uqw  = (const float*)d_in[6];
    const float* ukw  = (const float*)d_in[7];
    const float* uvw  = (const float*)d_in[8];
    const float* sq1  = (const float*)d_in[9];
    const float* sq2  = (const float*)d_in[10];
    const float* sk1  = (const float*)d_in[11];
    const float* sk2  = (const float*)d_in[12];
    const float* sv1  = (const float*)d_in[13];
    const float* sv2  = (const float*)d_in[14];
    const float* fcw  = (const float*)d_in[15];
    const float* ln1g = (const float*)d_in[16];
    const float* ln1b = (const float*)d_in[17];
    const float* ffn1 = (const float*)d_in[18];
    const float* ffn2 = (const float*)d_in[19];
    const float* ln2g = (const float*)d_in[20];
    const float* ln2b = (const float*)d_in[21];

    float* res  = (float*)d_out;
    float* attn = res + (size_t)NB * SEQ * DM;

    cudaFuncSetAttribute(proj_kernel,  cudaFuncAttributeMaxDynamicSharedMemorySize, PROJ_SMEM_BYTES);
    cudaFuncSetAttribute(attn2_kernel, cudaFuncAttributeMaxDynamicSharedMemorySize, ATT_SMEM_BYTES);
    cudaFuncSetAttribute(post_kernel,  cudaFuncAttributeMaxDynamicSharedMemorySize, POST_SMEM_BYTES);

    detect_mask_kernel<<<1, 32>>>((const unsigned char*)mask);
    convert_mask_kernel<<<(NB * SEQ * 64) / 256, 256>>>(mask);
    gates_kernel<<<NB, 32>>>(u, sq1, sq2, sk1, sk2, sv1, sv2);
    proj_kernel<<<(NB * SEQ) / 64, 256, PROJ_SMEM_BYTES>>>(x, wq, wk, wv, uqw, ukw, uvw);
    attn2_kernel<<<NB * NH * (SEQ / TQ), 512, ATT_SMEM_BYTES>>>(attn);
    norm_kernel<<<NB * NH * SEQ, 128>>>(attn);
    post_kernel<<<(NB * SEQ) / 64, 256, POST_SMEM_BYTES>>>(x, fcw, ln1g, ln1b, ffn1, ffn2,
                                                           ln2g, ln2b, res);
}